// round 13
// baseline (speedup 1.0000x reference)
#include <cuda_runtime.h>
#include <cuda_bf16.h>
#include <cstdint>

#define NN 100000
#define NE 800000
#define HD 128
#define SLOTS 64           // padded adjacency slots per node (Poisson(8): P(deg>40) ~ 1e-16)
#define BN_EPS 1e-5f

// ---------------- scratch (module globals; no cudaMalloc) ----------------
__device__ __align__(256) float g_xs[(size_t)NN * HD];     // dinv[i] * (x @ W)[i]
__device__ __align__(256) float g_agg[(size_t)NN * HD];    // pre-BN activations
__device__ __align__(256) int   g_src[(size_t)NN * SLOTS]; // padded incoming-edge source ids
__device__ __align__(256) int   g_cnt[NN];                 // incoming edge count (no self-loop)
__device__ __align__(256) float g_dinv[NN];
__device__ __align__(256) float g_sum[HD];
__device__ __align__(256) float g_sumsq[HD];
__device__ __align__(256) float g_scale[HD];
__device__ __align__(256) float g_shift[HD];
__device__ int g_is64;                                     // edge-index dtype flag

// ---------------- dtype detect: int64 indices have zero odd 32b words ----
__global__ void k_detect(const int* __restrict__ ew, int nwords) {
    // nwords = 2*E (safe lower bound for both dtypes). Sample odd words.
    int i = threadIdx.x;                 // 0..255
    int nz = 0;
    for (int j = 1 + 2 * i; j < nwords && j < 8192; j += 512)
        nz |= (ew[j] != 0);
    // warp+block reduce via ballot on shared flag
    __shared__ int s_nz;
    if (threadIdx.x == 0) s_nz = 0;
    __syncthreads();
    if (nz) atomicOr(&s_nz, 1);
    __syncthreads();
    if (threadIdx.x == 0) g_is64 = (s_nz == 0) ? 1 : 0;
}

// ---------------- init: zero counters + BN accumulators ------------------
__global__ void k_zero(int n) {
    int i = blockIdx.x * blockDim.x + threadIdx.x;
    if (i < n) g_cnt[i] = 0;
    if (i < HD) { g_sum[i] = 0.f; g_sumsq[i] = 0.f; }
}

// ---------------- build padded adjacency: src lists per target -----------
__global__ void k_fill(const void* __restrict__ ei, int E, int n) {
    int i = blockIdx.x * blockDim.x + threadIdx.x;
    if (i >= E) return;
    int r, c;
    if (g_is64) {
        const long long* e64 = (const long long*)ei;
        r = (int)e64[i];
        c = (int)e64[(size_t)E + i];
    } else {
        const int* e32 = (const int*)ei;
        r = e32[i];
        c = e32[(size_t)E + i];
    }
    if ((unsigned)r >= (unsigned)n || (unsigned)c >= (unsigned)n) return;  // never trap
    int pos = atomicAdd(&g_cnt[c], 1);
    if (pos < SLOTS) g_src[(size_t)c * SLOTS + pos] = r;
}

// ---------------- dinv = rsqrt(deg), deg = incoming + self-loop ----------
__global__ void k_dinv(int n) {
    int i = blockIdx.x * blockDim.x + threadIdx.x;
    if (i < n) g_dinv[i] = rsqrtf((float)(g_cnt[i] + 1));
}

// ---------------- GEMM: xs = dinv * (x @ W) -------------------------------
// block = 256 threads, tile = 64 rows x 128 cols. W (64KB) + X tile (32KB) smem.
__global__ void __launch_bounds__(256, 2)
k_gemm(const float* __restrict__ x, const float* __restrict__ W, int n) {
    extern __shared__ float sm[];
    float* Wsh = sm;                 // 128*128 = 16384 floats
    float* Xsh = sm + 16384;         // 64*128  =  8192 floats
    float* Dsh = sm + 16384 + 8192;  // 64 floats

    const int tid = threadIdx.x;
    const int row0 = blockIdx.x * 64;

    for (int j = tid; j < 4096; j += 256)
        ((float4*)Wsh)[j] = ((const float4*)W)[j];

    const float4 z4 = make_float4(0.f, 0.f, 0.f, 0.f);
    for (int j = tid; j < 2048; j += 256) {
        int r = j >> 5;
        int kq = j & 31;
        int gr = row0 + r;
        ((float4*)Xsh)[j] = (gr < n) ? ((const float4*)x)[(size_t)gr * 32 + kq] : z4;
    }
    if (tid < 64) {
        int gr = row0 + tid;
        Dsh[tid] = (gr < n) ? g_dinv[gr] : 0.f;
    }
    __syncthreads();

    const int tx = tid & 31;
    const int ty = tid >> 5;
    const int rbase = ty * 8;

    float acc[8][4];
#pragma unroll
    for (int i = 0; i < 8; i++)
#pragma unroll
        for (int j = 0; j < 4; j++) acc[i][j] = 0.f;

#pragma unroll 4
    for (int k = 0; k < 128; k++) {
        float4 w4 = *(const float4*)(Wsh + k * 128 + tx * 4);
#pragma unroll
        for (int i = 0; i < 8; i++) {
            float xv = Xsh[(rbase + i) * 128 + k];
            acc[i][0] = fmaf(xv, w4.x, acc[i][0]);
            acc[i][1] = fmaf(xv, w4.y, acc[i][1]);
            acc[i][2] = fmaf(xv, w4.z, acc[i][2]);
            acc[i][3] = fmaf(xv, w4.w, acc[i][3]);
        }
    }

#pragma unroll
    for (int i = 0; i < 8; i++) {
        int gr = row0 + rbase + i;
        if (gr < n) {
            float d = Dsh[rbase + i];
            float4 v = make_float4(acc[i][0] * d, acc[i][1] * d,
                                   acc[i][2] * d, acc[i][3] * d);
            *(float4*)(g_xs + (size_t)gr * HD + tx * 4) = v;
        }
    }
}

// ---------------- gather aggregation: one warp per node ------------------
// agg[i] = dinv[i] * ( xs[i] + sum_{e: col(e)=i} xs[row(e)] )
__global__ void k_agg(int n) {
    int warp = (blockIdx.x * blockDim.x + threadIdx.x) >> 5;
    int lane = threadIdx.x & 31;
    if (warp >= n) return;

    int cnt = g_cnt[warp];
    if (cnt > SLOTS) cnt = SLOTS;
    float d = g_dinv[warp];
    size_t base = (size_t)warp * SLOTS;

    // self-loop message
    float4 acc = *((const float4*)(g_xs + (size_t)warp * HD) + lane);

    // prefetch up to 32 source ids, one per lane; broadcast via shfl
    int srcj = (lane < cnt) ? g_src[base + lane] : 0;
    int m = cnt < 32 ? cnt : 32;
    for (int j = 0; j < m; j++) {
        int s = __shfl_sync(0xffffffffu, srcj, j);
        float4 v = *((const float4*)(g_xs + (size_t)s * HD) + lane);
        acc.x += v.x; acc.y += v.y; acc.z += v.z; acc.w += v.w;
    }
    for (int j = 32; j < cnt; j++) {           // rare tail (deg > 32)
        int s = g_src[base + j];
        float4 v = *((const float4*)(g_xs + (size_t)s * HD) + lane);
        acc.x += v.x; acc.y += v.y; acc.z += v.z; acc.w += v.w;
    }

    acc.x *= d; acc.y *= d; acc.z *= d; acc.w *= d;
    *((float4*)(g_agg + (size_t)warp * HD) + lane) = acc;
}

// ---------------- BN batch statistics -------------------------------------
__global__ void k_stats(int n) {
    int f = threadIdx.x;  // 0..127
    int rpb = (n + gridDim.x - 1) / gridDim.x;
    int r0 = blockIdx.x * rpb;
    int r1 = min(r0 + rpb, n);
    float s = 0.f, s2 = 0.f;
    for (int r = r0; r < r1; r++) {
        float v = g_agg[(size_t)r * HD + f];
        s += v;
        s2 = fmaf(v, v, s2);
    }
    atomicAdd(&g_sum[f], s);
    atomicAdd(&g_sumsq[f], s2);
}

// bias b shifts every row of a feature uniformly -> BatchNorm removes it
// exactly, so it is never applied.
__global__ void k_bnfin(const float* __restrict__ gamma,
                        const float* __restrict__ beta, int n) {
    int f = threadIdx.x;
    float inv_n = 1.0f / (float)n;
    float mean = g_sum[f] * inv_n;
    float var = fmaf(-mean, mean, g_sumsq[f] * inv_n);
    float sc = gamma[f] * rsqrtf(var + BN_EPS);
    g_scale[f] = sc;
    g_shift[f] = fmaf(-mean, sc, beta[f]);
}

// ---------------- epilogue: out = relu(agg*scale + shift) ----------------
__global__ void k_out(float* __restrict__ out, int n) {
    int idx = blockIdx.x * blockDim.x + threadIdx.x;  // float4 index
    int total = n * (HD / 4);
    if (idx >= total) return;
    int fq = idx & 31;
    float4 a = ((const float4*)g_agg)[idx];
    float4 sc = ((const float4*)g_scale)[fq];
    float4 sh = ((const float4*)g_shift)[fq];
    float4 o;
    o.x = fmaxf(fmaf(a.x, sc.x, sh.x), 0.f);
    o.y = fmaxf(fmaf(a.y, sc.y, sh.y), 0.f);
    o.z = fmaxf(fmaf(a.z, sc.z, sh.z), 0.f);
    o.w = fmaxf(fmaf(a.w, sc.w, sh.w), 0.f);
    ((float4*)out)[idx] = o;
}

// --------------------------------------------------------------------------
extern "C" void kernel_launch(void* const* d_in, const int* in_sizes, int n_in,
                              void* d_out, int out_size) {
    const float* x      = (const float*)d_in[0];
    const void*  ei     = d_in[1];                 // int32 or int64, detected on device
    const float* W      = (const float*)d_in[2];
    // d_in[3] = b (cancels under BatchNorm; unused)
    const float* gamma  = (const float*)d_in[4];
    const float* beta   = (const float*)d_in[5];
    float* out          = (float*)d_out;

    const int n = in_sizes[0] / HD;   // 100000
    const int E = in_sizes[1] / 2;    // 800000 (element count is dtype-independent)

    const int smem_gemm = (16384 + 8192 + 64) * (int)sizeof(float);
    cudaFuncSetAttribute(k_gemm, cudaFuncAttributeMaxDynamicSharedMemorySize,
                         smem_gemm);

    k_detect<<<1, 256>>>((const int*)ei, 2 * E);
    k_zero<<<(n + 255) / 256, 256>>>(n);
    k_fill<<<(E + 255) / 256, 256>>>(ei, E, n);
    k_dinv<<<(n + 255) / 256, 256>>>(n);
    k_gemm<<<(n + 63) / 64, 256, smem_gemm>>>(x, W, n);
    k_agg<<<(n + 7) / 8, 256>>>(n);           // one warp per node
    k_stats<<<512, HD>>>(n);
    k_bnfin<<<1, HD>>>(gamma, beta, n);
    k_out<<<(n * (HD / 4) + 255) / 256, 256>>>(out, n);
}